// round 1
// baseline (speedup 1.0000x reference)
#include <cuda_runtime.h>
#include <math_constants.h>

#define NP   16384
#define SEG  512      // db points per segment (per blockIdx.y)
#define TPB  256
#define QPT  8        // queries per thread (4 packed f32x2 pairs)
#define QPB  (TPB*QPT) // 2048 queries per block

// ---------------- device scratch (no allocs allowed) ----------------
__device__ int   g_min_i[2 * NP];     // per-query min squared dist (float bits, >=0)
__device__ float g_part_dist[128];
__device__ float g_part_col[128];

// ---------------- f32x2 packed helpers (sm_103a) ----------------
__device__ __forceinline__ unsigned long long pk2(float lo, float hi) {
    unsigned long long r;
    asm("mov.b64 %0, {%1, %2};" : "=l"(r) : "f"(lo), "f"(hi));
    return r;
}
__device__ __forceinline__ void upk2(unsigned long long v, float& lo, float& hi) {
    asm("mov.b64 {%0, %1}, %2;" : "=f"(lo), "=f"(hi) : "l"(v));
}
__device__ __forceinline__ unsigned long long fma2(unsigned long long a,
                                                   unsigned long long b,
                                                   unsigned long long c) {
    unsigned long long d;
    asm("fma.rn.f32x2 %0, %1, %2, %3;" : "=l"(d) : "l"(a), "l"(b), "l"(c));
    return d;
}

// ---------------- kernel 0: init mins to +FLT_MAX ----------------
__global__ void init_kernel() {
    int i = blockIdx.x * blockDim.x + threadIdx.x;
    if (i < 2 * NP) g_min_i[i] = 0x7F7FFFFF;  // FLT_MAX bits
}

// ---------------- kernel 1: chamfer partial mins ----------------
// grid: (16, 32). blockIdx.x: [0..7]=forward (query=pred, db=gt),
// [8..15]=backward. blockIdx.y = db segment.
// Inner kernel per db point per query pair: t = fma2 chain of (g2 - 2*q.g);
// true sqdist = p2 + t, added once after the loop (argmin-invariant).
__global__ __launch_bounds__(TPB)
void chamfer_kernel(const float* __restrict__ pred, const float* __restrict__ gt) {
    __shared__ float4 s_db[2 * SEG];  // per point: (x,x,y,y), (z,z,g2,g2)

    const int tid   = threadIdx.x;
    const int dir   = blockIdx.x >> 3;
    const int qbase = (blockIdx.x & 7) * QPB;
    const float* __restrict__ qc  = dir ? gt   : pred;
    const float* __restrict__ dbc = dir ? pred : gt;

    // cooperative load + duplication of db segment
    const int segBase = blockIdx.y * SEG;
    for (int j = tid; j < SEG; j += TPB) {
        const float* r = dbc + (size_t)(segBase + j) * 6;
        float x = r[0], y = r[1], z = r[2];
        float g2 = x * x + y * y + z * z;
        s_db[2 * j]     = make_float4(x, x, y, y);
        s_db[2 * j + 1] = make_float4(z, z, g2, g2);
    }

    // load 8 queries (4 packed pairs), precompute -2*q and p2
    unsigned long long m2x[4], m2y[4], m2z[4];
    float p2[8], mn[8];
#pragma unroll
    for (int k = 0; k < 4; k++) {
        int q0 = qbase + tid + (2 * k) * TPB;
        int q1 = q0 + TPB;
        const float* r0 = qc + (size_t)q0 * 6;
        const float* r1 = qc + (size_t)q1 * 6;
        float x0 = r0[0], y0 = r0[1], z0 = r0[2];
        float x1 = r1[0], y1 = r1[1], z1 = r1[2];
        p2[2 * k]     = x0 * x0 + y0 * y0 + z0 * z0;
        p2[2 * k + 1] = x1 * x1 + y1 * y1 + z1 * z1;
        m2x[k] = pk2(-2.f * x0, -2.f * x1);
        m2y[k] = pk2(-2.f * y0, -2.f * y1);
        m2z[k] = pk2(-2.f * z0, -2.f * z1);
        mn[2 * k] = CUDART_INF_F;
        mn[2 * k + 1] = CUDART_INF_F;
    }
    __syncthreads();

    const ulonglong2* __restrict__ sdb = reinterpret_cast<const ulonglong2*>(s_db);
#pragma unroll 4
    for (int j = 0; j < SEG; j++) {
        ulonglong2 A = sdb[2 * j];      // A.x=(x,x) A.y=(y,y)
        ulonglong2 B = sdb[2 * j + 1];  // B.x=(z,z) B.y=(g2,g2)
#pragma unroll
        for (int k = 0; k < 4; k++) {
            unsigned long long t = fma2(m2z[k], B.x, B.y);
            t = fma2(m2y[k], A.y, t);
            t = fma2(m2x[k], A.x, t);
            float lo, hi;
            upk2(t, lo, hi);
            mn[2 * k]     = fminf(mn[2 * k], lo);
            mn[2 * k + 1] = fminf(mn[2 * k + 1], hi);
        }
    }

    // add p2, clamp >= 0 (monotone, so order with global min commutes),
    // then exact int-bit atomicMin (valid for non-negative floats)
#pragma unroll
    for (int k = 0; k < 4; k++) {
        int q0 = qbase + tid + (2 * k) * TPB;
        float d0 = fmaxf(p2[2 * k] + mn[2 * k], 0.0f);
        float d1 = fmaxf(p2[2 * k + 1] + mn[2 * k + 1], 0.0f);
        atomicMin(&g_min_i[dir * NP + q0],       __float_as_int(d0));
        atomicMin(&g_min_i[dir * NP + q0 + TPB], __float_as_int(d1));
    }
}

// ---------------- kernel 2: partial reductions (deterministic) ----------------
// 128 blocks x 256 threads. Block b: dist entries [b*256,(b+1)*256),
// color entries [b*384,(b+1)*384) of the 16384*3 color-diff array.
__global__ __launch_bounds__(256)
void reduce1_kernel(const float* __restrict__ pred, const float* __restrict__ gt) {
    __shared__ float sd[256];
    __shared__ float sc[256];
    const int b = blockIdx.x, t = threadIdx.x;

    float v = __int_as_float(g_min_i[b * 256 + t]);
    float dist = sqrtf(fmaxf(v, 0.0f));

    float col = 0.0f;
    {
        int ce = b * 384 + t;
        int i = ce / 3, c = ce - 3 * i;
        col += fabsf(pred[(size_t)i * 6 + 3 + c] - gt[(size_t)i * 6 + 3 + c]);
        if (t < 128) {
            int ce1 = ce + 256;
            int i1 = ce1 / 3, c1 = ce1 - 3 * i1;
            col += fabsf(pred[(size_t)i1 * 6 + 3 + c1] - gt[(size_t)i1 * 6 + 3 + c1]);
        }
    }

    sd[t] = dist;
    sc[t] = col;
    __syncthreads();
#pragma unroll
    for (int s = 128; s > 0; s >>= 1) {
        if (t < s) { sd[t] += sd[t + s]; sc[t] += sc[t + s]; }
        __syncthreads();
    }
    if (t == 0) {
        g_part_dist[b] = sd[0];
        g_part_col[b]  = sc[0];
    }
}

// ---------------- kernel 3: final combine ----------------
__global__ void reduce2_kernel(float* __restrict__ out) {
    __shared__ float sd[128];
    __shared__ float sc[128];
    const int t = threadIdx.x;  // 128 threads
    sd[t] = g_part_dist[t];
    sc[t] = g_part_col[t];
    __syncthreads();
#pragma unroll
    for (int s = 64; s > 0; s >>= 1) {
        if (t < s) { sd[t] += sd[t + s]; sc[t] += sc[t + s]; }
        __syncthreads();
    }
    if (t == 0) {
        // chamfer = mean_fwd + mean_bwd = (sum_fwd + sum_bwd) / NP (equal counts)
        out[0] = sd[0] * (1.0f / (float)NP) + 0.1f * sc[0] * (1.0f / (float)(NP * 3));
    }
}

extern "C" void kernel_launch(void* const* d_in, const int* in_sizes, int n_in,
                              void* d_out, int out_size) {
    const float* pred = (const float*)d_in[0];
    const float* gt   = (const float*)d_in[1];
    float* out        = (float*)d_out;
    (void)in_sizes; (void)n_in; (void)out_size;

    init_kernel<<<128, 256>>>();
    dim3 grid(16, 32);
    chamfer_kernel<<<grid, TPB>>>(pred, gt);
    reduce1_kernel<<<128, 256>>>(pred, gt);
    reduce2_kernel<<<1, 128>>>(out);
}

// round 2
// speedup vs baseline: 1.0400x; 1.0400x over previous
#include <cuda_runtime.h>
#include <math_constants.h>

#define NP   16384
#define PT   64        // preds per tile
#define GTL  512       // gts per tile
#define TPB  256

typedef unsigned long long u64;

// ---------------- device scratch (no allocs allowed) ----------------
__device__ int   g_min_i[2 * NP];     // [0..NP): fwd (per-pred) mins; [NP..2NP): bwd (per-gt)
__device__ float g_part_dist[128];
__device__ float g_part_col[128];

// ---------------- f32x2 packed helpers (sm_103a) ----------------
__device__ __forceinline__ u64 pk2(float lo, float hi) {
    u64 r;
    asm("mov.b64 %0, {%1, %2};" : "=l"(r) : "f"(lo), "f"(hi));
    return r;
}
__device__ __forceinline__ void upk2(u64 v, float& lo, float& hi) {
    asm("mov.b64 {%0, %1}, %2;" : "=f"(lo), "=f"(hi) : "l"(v));
}
__device__ __forceinline__ u64 fma2(u64 a, u64 b, u64 c) {
    u64 d;
    asm("fma.rn.f32x2 %0, %1, %2, %3;" : "=l"(d) : "l"(a), "l"(b), "l"(c));
    return d;
}
__device__ __forceinline__ u64 add2(u64 a, u64 b) {
    u64 d;
    asm("add.rn.f32x2 %0, %1, %2;" : "=l"(d) : "l"(a), "l"(b));
    return d;
}

// ---------------- kernel 0: init mins to +FLT_MAX ----------------
__global__ void init_kernel() {
    int i = blockIdx.x * blockDim.x + threadIdx.x;
    if (i < 2 * NP) g_min_i[i] = 0x7F7FFFFF;  // FLT_MAX bits
}

// ---------------- kernel 1: symmetric chamfer tiles ----------------
// Each block computes a PT x GTL tile of the pairwise sq-dist matrix ONCE and
// updates both per-pred (row) and per-gt (col) mins.
// Thread layout: ty = warp (8 pred octets... PT=64 -> ty*8 preds), tx = lane.
// Thread owns preds [ty*8, ty*8+8) as 4 packed pairs, and gts j*32+tx, j=0..15.
__global__ __launch_bounds__(TPB, 2)
void chamfer_kernel(const float* __restrict__ pred, const float* __restrict__ gt) {
    __shared__ ulonglong2 sgt_a[GTL];   // (xx, yy) duplicated pairs
    __shared__ ulonglong2 sgt_b[GTL];   // (zz, g2g2)
    __shared__ float4     spred[PT];    // (x, y, z, p2)
    __shared__ float      scol[8 * GTL];

    const int tid = threadIdx.x;
    const int tx = tid & 31;
    const int ty = tid >> 5;
    const int predBase = blockIdx.y * PT;
    const int gtBase   = blockIdx.x * GTL;

    // cooperative load of gt tile (duplicated packing for f32x2)
    for (int g = tid; g < GTL; g += TPB) {
        const float* r = gt + (size_t)(gtBase + g) * 6;
        float x = r[0], y = r[1], z = r[2];
        float g2 = x * x + y * y + z * z;
        ulonglong2 a, b;
        a.x = pk2(x, x);  a.y = pk2(y, y);
        b.x = pk2(z, z);  b.y = pk2(g2, g2);
        sgt_a[g] = a;
        sgt_b[g] = b;
    }
    // pred tile
    if (tid < PT) {
        const float* r = pred + (size_t)(predBase + tid) * 6;
        float x = r[0], y = r[1], z = r[2];
        spred[tid] = make_float4(x, y, z, x * x + y * y + z * z);
    }
    __syncthreads();

    // per-thread pred registers: -2*coord packed pairs + packed p2
    u64 m2x[4], m2y[4], m2z[4], P2[4];
    float rmin[8];
#pragma unroll
    for (int k = 0; k < 4; k++) {
        float4 a = spred[ty * 8 + 2 * k];
        float4 b = spred[ty * 8 + 2 * k + 1];
        m2x[k] = pk2(-2.f * a.x, -2.f * b.x);
        m2y[k] = pk2(-2.f * a.y, -2.f * b.y);
        m2z[k] = pk2(-2.f * a.z, -2.f * b.z);
        P2[k]  = pk2(a.w, b.w);
        rmin[2 * k]     = CUDART_INF_F;
        rmin[2 * k + 1] = CUDART_INF_F;
    }

    float cmin[16];
#pragma unroll
    for (int j = 0; j < 16; j++) {
        ulonglong2 A = sgt_a[j * 32 + tx];   // (xx, yy)
        ulonglong2 B = sgt_b[j * 32 + tx];   // (zz, g2g2)
        float c = CUDART_INF_F;
#pragma unroll
        for (int k = 0; k < 4; k++) {
            u64 t = fma2(m2z[k], B.x, B.y);      // g2 - 2 z qz
            t = fma2(m2y[k], A.y, t);
            t = fma2(m2x[k], A.x, t);            // t = g2 - 2 q.g (2 preds)
            float tl, th;
            upk2(t, tl, th);
            rmin[2 * k]     = fminf(rmin[2 * k], tl);       // row: defer p2
            rmin[2 * k + 1] = fminf(rmin[2 * k + 1], th);
            u64 rr = add2(t, P2[k]);             // full d^2 for col compare
            float cl, ch;
            upk2(rr, cl, ch);
            c = fminf(c, fminf(cl, ch));
        }
        cmin[j] = c;
    }

    // -------- col side: cross-warp (ty) reduce via smem --------
#pragma unroll
    for (int j = 0; j < 16; j++)
        scol[ty * GTL + j * 32 + tx] = cmin[j];

    // -------- row side: add p2, butterfly min over 32 lanes --------
#pragma unroll
    for (int k = 0; k < 4; k++) {
        float pl, ph;
        upk2(P2[k], pl, ph);
        rmin[2 * k]     += pl;
        rmin[2 * k + 1] += ph;
    }
#pragma unroll
    for (int s = 16; s > 0; s >>= 1) {
#pragma unroll
        for (int i = 0; i < 8; i++)
            rmin[i] = fminf(rmin[i], __shfl_xor_sync(0xffffffffu, rmin[i], s));
    }
    if (tx == 0) {
#pragma unroll
        for (int i = 0; i < 8; i++)
            atomicMin(&g_min_i[predBase + ty * 8 + i],
                      __float_as_int(fmaxf(rmin[i], 0.0f)));
    }

    __syncthreads();
#pragma unroll
    for (int g = tid; g < GTL; g += TPB) {   // 2 iterations
        float m = scol[g];
#pragma unroll
        for (int s = 1; s < 8; s++) m = fminf(m, scol[s * GTL + g]);
        atomicMin(&g_min_i[NP + gtBase + g],
                  __float_as_int(fmaxf(m, 0.0f)));
    }
}

// ---------------- kernel 2: partial reductions (deterministic) ----------------
__global__ __launch_bounds__(256)
void reduce1_kernel(const float* __restrict__ pred, const float* __restrict__ gt) {
    __shared__ float sd[256];
    __shared__ float sc[256];
    const int b = blockIdx.x, t = threadIdx.x;

    float v = __int_as_float(g_min_i[b * 256 + t]);
    float dist = sqrtf(fmaxf(v, 0.0f));

    float col = 0.0f;
    {
        int ce = b * 384 + t;
        int i = ce / 3, c = ce - 3 * i;
        col += fabsf(pred[(size_t)i * 6 + 3 + c] - gt[(size_t)i * 6 + 3 + c]);
        if (t < 128) {
            int ce1 = ce + 256;
            int i1 = ce1 / 3, c1 = ce1 - 3 * i1;
            col += fabsf(pred[(size_t)i1 * 6 + 3 + c1] - gt[(size_t)i1 * 6 + 3 + c1]);
        }
    }

    sd[t] = dist;
    sc[t] = col;
    __syncthreads();
#pragma unroll
    for (int s = 128; s > 0; s >>= 1) {
        if (t < s) { sd[t] += sd[t + s]; sc[t] += sc[t + s]; }
        __syncthreads();
    }
    if (t == 0) {
        g_part_dist[b] = sd[0];
        g_part_col[b]  = sc[0];
    }
}

// ---------------- kernel 3: final combine ----------------
__global__ void reduce2_kernel(float* __restrict__ out) {
    __shared__ float sd[128];
    __shared__ float sc[128];
    const int t = threadIdx.x;  // 128 threads
    sd[t] = g_part_dist[t];
    sc[t] = g_part_col[t];
    __syncthreads();
#pragma unroll
    for (int s = 64; s > 0; s >>= 1) {
        if (t < s) { sd[t] += sd[t + s]; sc[t] += sc[t + s]; }
        __syncthreads();
    }
    if (t == 0) {
        out[0] = sd[0] * (1.0f / (float)NP) + 0.1f * sc[0] * (1.0f / (float)(NP * 3));
    }
}

extern "C" void kernel_launch(void* const* d_in, const int* in_sizes, int n_in,
                              void* d_out, int out_size) {
    const float* pred = (const float*)d_in[0];
    const float* gt   = (const float*)d_in[1];
    float* out        = (float*)d_out;
    (void)in_sizes; (void)n_in; (void)out_size;

    init_kernel<<<128, 256>>>();
    dim3 grid(NP / GTL, NP / PT);   // (32, 256) = 8192 blocks
    chamfer_kernel<<<grid, TPB>>>(pred, gt);
    reduce1_kernel<<<128, 256>>>(pred, gt);
    reduce2_kernel<<<1, 128>>>(out);
}